// round 6
// baseline (speedup 1.0000x reference)
#include <cuda_runtime.h>
#include <cstdint>

// out[n] = realism(std(chunks[n])) + 0.15 + 0.2*cos(chunks[n,:10,:], prev[118:,:])
// chunks: [4096,128,64] f32 (32KB/chunk), prev: [128,64] f32, out: [4096] f32
//
// One CTA per chunk. 4 x 8KB cp.async.bulk stages, all issued up-front with
// independent mbarriers: compute on stage s overlaps arrival of stages s+1..3.
// No __syncthreads in the consume path (single-use buffers).

#define STAGES 4
#define STAGE_BYTES 8192u
#define STAGE_F4 512            // float4 per stage
#define F4_PER_THREAD 2         // 512 / 256

__device__ __forceinline__ uint32_t smem_u32(const void* p) {
    uint32_t a;
    asm("{ .reg .u64 t; cvta.to.shared.u64 t, %1; cvt.u32.u64 %0, t; }" : "=r"(a) : "l"(p));
    return a;
}
__device__ __forceinline__ void fma2(unsigned long long& acc, unsigned long long a, unsigned long long b) {
    asm("fma.rn.f32x2 %0, %1, %2, %0;" : "+l"(acc) : "l"(a), "l"(b));
}
__device__ __forceinline__ void add2(unsigned long long& acc, unsigned long long a) {
    asm("add.rn.f32x2 %0, %0, %1;" : "+l"(acc) : "l"(a));
}
__device__ __forceinline__ float hsum2(unsigned long long v) {
    float lo, hi;
    asm("mov.b64 {%0,%1}, %2;" : "=f"(lo), "=f"(hi) : "l"(v));
    return lo + hi;
}
__device__ __forceinline__ void mbar_wait0(uint32_t mbar_a) {
    uint32_t done;
    asm volatile(
        "{\n\t.reg .pred p;\n\t"
        "mbarrier.try_wait.parity.acquire.cta.shared::cta.b64 p, [%1], 0;\n\t"
        "selp.b32 %0, 1, 0, p;\n\t}"
        : "=r"(done) : "r"(mbar_a) : "memory");
    if (!done) {
        asm volatile(
            "{\n\t.reg .pred P1;\n\t"
            "W_%=:\n\t"
            "mbarrier.try_wait.parity.acquire.cta.shared::cta.b64 P1, [%0], 0, 0x989680;\n\t"
            "@P1 bra.uni D_%=;\n\t"
            "bra.uni W_%=;\n\t"
            "D_%=:\n\t}"
            :: "r"(mbar_a) : "memory");
    }
}

__global__ __launch_bounds__(256, 6) void chunk_ranker_kernel(
    const float* __restrict__ chunks,
    const float* __restrict__ prev,
    float* __restrict__ out)
{
    __shared__ __align__(128) float tile[8192];              // 32 KB
    __shared__ __align__(8) unsigned long long mbar[STAGES];
    __shared__ float red[8][5];

    const int n = blockIdx.x;
    const int t = threadIdx.x;
    const uint32_t tile_a = smem_u32(tile);
    const uint32_t mbar_a0 = smem_u32(&mbar[0]);

    if (t == 0) {
        #pragma unroll
        for (int s = 0; s < STAGES; s++) {
            asm volatile("mbarrier.init.shared.b64 [%0], 1;"
                         :: "r"(mbar_a0 + 8u * s) : "memory");
        }
    }
    __syncthreads();   // mbarriers visible to all threads before any wait

    if (t == 0) {
        const float* src = chunks + (size_t)n * 8192;
        #pragma unroll
        for (int s = 0; s < STAGES; s++) {
            const uint32_t mb = mbar_a0 + 8u * s;
            asm volatile("mbarrier.arrive.expect_tx.shared.b64 _, [%0], %1;"
                         :: "r"(mb), "r"(STAGE_BYTES) : "memory");
            asm volatile("cp.async.bulk.shared::cta.global.mbarrier::complete_tx::bytes "
                         "[%0], [%1], %2, [%3];"
                         :: "r"(tile_a + STAGE_BYTES * s),
                            "l"(src + 2048 * s),
                            "r"(STAGE_BYTES), "r"(mb) : "memory");
        }
    }

    const ulonglong2* tile2 = reinterpret_cast<const ulonglong2*>(tile);
    unsigned long long sum2 = 0ull, sqa = 0ull, sqb = 0ull;
    unsigned long long dot2 = 0ull, ssq2 = 0ull, csq2 = 0ull;

    #pragma unroll
    for (int s = 0; s < STAGES; s++) {
        mbar_wait0(mbar_a0 + 8u * s);

        // Prefix (first 160 float4 of the chunk) lives entirely in stage 0.
        if (s == 0 && t < 160) {
            ulonglong2 v = tile2[t];
            ulonglong2 c = __ldg(reinterpret_cast<const ulonglong2*>(prev + 118 * 64) + t);
            fma2(dot2, v.x, c.x); fma2(dot2, v.y, c.y);
            fma2(ssq2, v.x, v.x); fma2(ssq2, v.y, v.y);
            fma2(csq2, c.x, c.x); fma2(csq2, c.y, c.y);
        }
        #pragma unroll
        for (int i = 0; i < F4_PER_THREAD; i++) {
            ulonglong2 v = tile2[s * STAGE_F4 + t + 256 * i];
            add2(sum2, v.x); add2(sum2, v.y);
            fma2(sqa, v.x, v.x); fma2(sqb, v.y, v.y);
        }
    }

    float sum = hsum2(sum2);
    float sq  = hsum2(sqa) + hsum2(sqb);
    float dot = hsum2(dot2);
    float ssq = hsum2(ssq2);
    float csq = hsum2(csq2);

    #pragma unroll
    for (int off = 16; off > 0; off >>= 1) {
        sum += __shfl_down_sync(0xffffffffu, sum, off);
        sq  += __shfl_down_sync(0xffffffffu, sq,  off);
        dot += __shfl_down_sync(0xffffffffu, dot, off);
        ssq += __shfl_down_sync(0xffffffffu, ssq, off);
        csq += __shfl_down_sync(0xffffffffu, csq, off);
    }

    const int wid = t >> 5, lid = t & 31;
    if (lid == 0) {
        red[wid][0] = sum; red[wid][1] = sq; red[wid][2] = dot;
        red[wid][3] = ssq; red[wid][4] = csq;
    }
    __syncthreads();

    if (t == 0) {
        float S = 0.f, Q = 0.f, D = 0.f, SS = 0.f, CS = 0.f;
        #pragma unroll
        for (int w = 0; w < 8; w++) {
            S += red[w][0]; Q += red[w][1]; D += red[w][2];
            SS += red[w][3]; CS += red[w][4];
        }
        const float M = 8192.0f;
        float var = (Q - S * S / M) / (M - 1.0f);
        float sd = sqrtf(fmaxf(var, 0.0f));

        float realism;
        if (sd < 0.01f)      realism = sd * 10.0f;
        else if (sd > 0.5f)  realism = 0.5f / sd;
        else                 realism = 1.0f - fabsf(sd - 0.1f);

        float denom = fmaxf(sqrtf(SS) * sqrtf(CS), 1e-8f);
        float boundary = D / denom;

        out[n] = realism + 0.3f * 0.5f + 0.2f * boundary;
    }
}

extern "C" void kernel_launch(void* const* d_in, const int* in_sizes, int n_in,
                              void* d_out, int out_size)
{
    const float* chunks = (const float*)d_in[0];   // [4096,128,64] f32
    // d_in[1] = regime_probs [9] — unused (constant 0.5 consistency)
    const float* prev = (const float*)d_in[2];     // [128,64] f32
    float* out = (float*)d_out;                    // [4096] f32

    const int n_chunks = in_sizes[0] / (128 * 64); // 4096
    chunk_ranker_kernel<<<n_chunks, 256>>>(chunks, prev, out);
}